// round 6
// baseline (speedup 1.0000x reference)
#include <cuda_runtime.h>
#include <cuda_bf16.h>

// Problem constants
#define B_   128
#define T_   512
#define E_   512
#define U_   1024
#define N4_  4096
#define V_   50257
#define NCTA_REC 128

// ---------------------------------------------------------------------------
// Device scratch
// ---------------------------------------------------------------------------
__device__ __nv_bfloat16  g_xz[268435456];          // (B*T, 4U) bf16 = 512 MB
__device__ __nv_bfloat16  g_embB[V_ * E_];          // emb table bf16
__device__ __nv_bfloat16  g_WxT[N4_ * E_];          // Wx^T (n,k) bf16
__device__ __nv_bfloat16  g_WhT[N4_ * U_];          // Wh^T (n,k) bf16
__device__ __nv_bfloat16  g_hb[2][B_ * U_];         // hidden state bf16, dbl-buffered
__device__ float          g_hfinal[B_ * U_];
__device__ int            g_tok[B_ * T_];
__device__ unsigned       g_cflag[T_][16];          // per-(step, chunk) producer counters

// ---------------------------------------------------------------------------
// Helpers
// ---------------------------------------------------------------------------
__device__ __forceinline__ float sigf(float x) { return 1.0f / (1.0f + __expf(-x)); }

__device__ __forceinline__ unsigned su32(const void* p) {
    return (unsigned)__cvta_generic_to_shared(p);
}
__device__ __forceinline__ void cpa16(unsigned dst, const void* src) {
    asm volatile("cp.async.cg.shared.global [%0], [%1], 16;\n" :: "r"(dst), "l"(src));
}
__device__ __forceinline__ void cpcommit() { asm volatile("cp.async.commit_group;\n"); }
#define CPWAIT(n) asm volatile("cp.async.wait_group %0;\n" :: "n"(n))

__device__ __forceinline__ void ldsm4(unsigned* r, unsigned addr) {
    asm volatile("ldmatrix.sync.aligned.m8n8.x4.shared.b16 {%0,%1,%2,%3}, [%4];\n"
        : "=r"(r[0]), "=r"(r[1]), "=r"(r[2]), "=r"(r[3]) : "r"(addr));
}
__device__ __forceinline__ void mma16816(float* c, const unsigned* a, unsigned b0, unsigned b1) {
    asm volatile(
        "mma.sync.aligned.m16n8k16.row.col.f32.bf16.bf16.f32 "
        "{%0,%1,%2,%3}, {%4,%5,%6,%7}, {%8,%9}, {%0,%1,%2,%3};\n"
        : "+f"(c[0]), "+f"(c[1]), "+f"(c[2]), "+f"(c[3])
        : "r"(a[0]), "r"(a[1]), "r"(a[2]), "r"(a[3]), "r"(b0), "r"(b1));
}
__device__ __forceinline__ float ldxz(const __nv_bfloat16* p) {
    unsigned short v;
    asm volatile("ld.global.cs.u16 %0, [%1];" : "=h"(v) : "l"(p));
    __nv_bfloat16_raw r; r.x = v;
    return __bfloat162float((__nv_bfloat16)r);
}
__device__ __forceinline__ void wait_chunk(const unsigned* p) {
    unsigned v;
    do {
        asm volatile("ld.acquire.gpu.global.u32 %0, [%1];" : "=r"(v) : "l"(p) : "memory");
    } while (v < 8u);
}

// ---------------------------------------------------------------------------
// Fused token detect + decode (int32/int64 robust; detection is per-block)
// ---------------------------------------------------------------------------
__global__ void tok_kernel(const int* __restrict__ s32) {
    __shared__ int snz;
    if (threadIdx.x == 0) snz = 0;
    __syncthreads();
    int nz = 0;
    for (int i = threadIdx.x; i < 1024; i += 256) nz |= s32[2 * i + 1];
    if (nz) atomicOr(&snz, 1);
    __syncthreads();
    const int is64 = (snz == 0);
    int i = blockIdx.x * blockDim.x + threadIdx.x;
    if (i < B_ * T_) {
        int t = is64 ? s32[2 * i] : s32[i];
        if (t < 0 || t >= V_) t = 0;
        g_tok[i] = t;
    }
}

// ---------------------------------------------------------------------------
// Prep kernels
// ---------------------------------------------------------------------------
__global__ void prep_emb(const float* __restrict__ emb) {
    int i = blockIdx.x * blockDim.x + threadIdx.x;
    if (i < (V_ * E_) / 4) {
        float4 v = *(const float4*)&emb[(size_t)i * 4];
        __nv_bfloat162 p0, p1;
        p0.x = __float2bfloat16(v.x); p0.y = __float2bfloat16(v.y);
        p1.x = __float2bfloat16(v.z); p1.y = __float2bfloat16(v.w);
        *(__nv_bfloat162*)&g_embB[(size_t)i * 4]     = p0;
        *(__nv_bfloat162*)&g_embB[(size_t)i * 4 + 2] = p1;
    }
}

__global__ void transpose_bf16(const float* __restrict__ src, __nv_bfloat16* __restrict__ dst,
                               int R, int C) {
    __shared__ float tile[32][33];
    int c0 = blockIdx.x * 32, r0 = blockIdx.y * 32;
    int tx = threadIdx.x, ty = threadIdx.y;
#pragma unroll
    for (int i = 0; i < 4; i++)
        tile[ty + 8 * i][tx] = src[(size_t)(r0 + ty + 8 * i) * C + c0 + tx];
    __syncthreads();
#pragma unroll
    for (int i = 0; i < 4; i++)
        dst[(size_t)(c0 + ty + 8 * i) * R + r0 + tx] = __float2bfloat16(tile[tx][ty + 8 * i]);
}

__global__ void init_state() {
    int i = blockIdx.x * blockDim.x + threadIdx.x;
    if (i < (B_ * U_) / 2) ((unsigned*)g_hb[0])[i] = 0u;
    if (i < T_ * 16) ((unsigned*)g_cflag)[i] = 0u;
}

// ---------------------------------------------------------------------------
// GEMM1: xz = embB[tok] @ Wx + b.  M=65536, N=4096, K=512. bf16 output.
// Tile 128x128, BK=64, 256 thr, 3-stage cp.async, ldmatrix + HMMA bf16.
// ---------------------------------------------------------------------------
#define GA_STRIDE (128 * 72)
#define GB_STRIDE (128 * 72)

__global__ void __launch_bounds__(256, 2)
gemm_xz(const float* __restrict__ bias) {
    extern __shared__ __nv_bfloat16 sm[];
    __nv_bfloat16* As = sm;
    __nv_bfloat16* Bs = sm + 3 * GA_STRIDE;
    __shared__ int   tok[128];
    __shared__ float bsm[128];

    const int tid   = threadIdx.x;
    const int lane  = tid & 31;
    const int warp  = tid >> 5;
    const int group = lane >> 2;
    const int tid4  = lane & 3;
    const int wm    = warp >> 1;
    const int wn    = warp & 1;
    const int m0 = blockIdx.y * 128;
    const int n0 = blockIdx.x * 128;

    if (tid < 128) tok[tid] = g_tok[m0 + tid];
    if (tid >= 128) bsm[tid - 128] = bias[n0 + tid - 128];
    __syncthreads();

    const unsigned AsAddr = su32(As);
    const unsigned BsAddr = su32(Bs);
    const int grpR = lane & 7, sel = lane >> 3;
    unsigned aoff[2];
#pragma unroll
    for (int mt = 0; mt < 2; mt++)
        aoff[mt] = ((wm * 32 + mt * 16 + grpR + (sel & 1) * 8) * 72 + (sel >> 1) * 8) * 2;
    unsigned boff[4];
#pragma unroll
    for (int p = 0; p < 4; p++)
        boff[p] = ((wn * 64 + p * 16 + grpR + (sel >> 1) * 8) * 72 + (sel & 1) * 8) * 2;

    auto issue = [&](int stage, int buf) {
        int k0 = stage * 64;
        unsigned adst = AsAddr + buf * GA_STRIDE * 2;
        unsigned bdst = BsAddr + buf * GB_STRIDE * 2;
#pragma unroll
        for (int i = 0; i < 4; i++) {
            int idx = tid + 256 * i;
            int r = idx >> 3, c = idx & 7;
            cpa16(adst + (r * 72 + c * 8) * 2, g_embB + (size_t)tok[r] * E_ + k0 + c * 8);
        }
#pragma unroll
        for (int i = 0; i < 4; i++) {
            int idx = tid + 256 * i;
            int r = idx >> 3, c = idx & 7;
            cpa16(bdst + (r * 72 + c * 8) * 2, g_WxT + (size_t)(n0 + r) * E_ + k0 + c * 8);
        }
        cpcommit();
    };

    float acc[2][8][4];
#pragma unroll
    for (int i = 0; i < 2; i++)
#pragma unroll
        for (int j = 0; j < 8; j++)
#pragma unroll
            for (int e = 0; e < 4; e++) acc[i][j][e] = 0.0f;

    issue(0, 0);
    issue(1, 1);

    for (int stg = 0; stg < 8; stg++) {
        if (stg < 7) { CPWAIT(1); } else { CPWAIT(0); }
        __syncthreads();
        if (stg + 2 < 8) issue(stg + 2, (stg + 2) % 3);

        unsigned abase = AsAddr + (stg % 3) * GA_STRIDE * 2;
        unsigned bbase = BsAddr + (stg % 3) * GB_STRIDE * 2;
#pragma unroll
        for (int kk4 = 0; kk4 < 4; kk4++) {
            unsigned koff = kk4 * 32;
            unsigned a[2][4];
            ldsm4(a[0], abase + aoff[0] + koff);
            ldsm4(a[1], abase + aoff[1] + koff);
#pragma unroll
            for (int p = 0; p < 4; p++) {
                unsigned bb[4];
                ldsm4(bb, bbase + boff[p] + koff);
#pragma unroll
                for (int mt = 0; mt < 2; mt++) {
                    mma16816(acc[mt][2 * p],     a[mt], bb[0], bb[1]);
                    mma16816(acc[mt][2 * p + 1], a[mt], bb[2], bb[3]);
                }
            }
        }
    }

#pragma unroll
    for (int mt = 0; mt < 2; mt++) {
#pragma unroll
        for (int nt = 0; nt < 8; nt++) {
            int gr = m0 + wm * 32 + mt * 16 + group;
            int gc = n0 + wn * 64 + nt * 8 + tid4 * 2;
            float bv0 = bsm[gc - n0], bv1 = bsm[gc - n0 + 1];
            __nv_bfloat162 p0, p1;
            p0.x = __float2bfloat16(acc[mt][nt][0] + bv0);
            p0.y = __float2bfloat16(acc[mt][nt][1] + bv1);
            p1.x = __float2bfloat16(acc[mt][nt][2] + bv0);
            p1.y = __float2bfloat16(acc[mt][nt][3] + bv1);
            *(__nv_bfloat162*)&g_xz[(size_t)gr * N4_ + gc]       = p0;
            *(__nv_bfloat162*)&g_xz[(size_t)(gr + 8) * N4_ + gc] = p1;
        }
    }
}

// ---------------------------------------------------------------------------
// Persistent LSTM recurrence. 128 CTAs = 2 m-halves x 64 u-groups, 256 thr.
// z[64][64] = h[64,1024] @ WhT[64,1024]^T (cols = 4 gates x 16 u).
// Wh slice resident in smem; A ring 3 x [64][72]; epilogue z-buffer aliases
// A ring. Inter-step sync: per-(step, k-chunk) producer counters (8 CTAs per
// chunk) polled just-in-time before each chunk's cp.async issue.
// ---------------------------------------------------------------------------
#define RA_STRIDE (64 * 72)
#define WH_PITCH  1032

__global__ void __launch_bounds__(256, 1)
lstm_recurrence() {
    extern __shared__ __nv_bfloat16 sm[];
    __nv_bfloat16* Whs  = sm;                    // [64][1032]
    __nv_bfloat16* Abuf = sm + 64 * WH_PITCH;    // 3 x [64][72]
    float* zbuf = (float*)Abuf;                  // [64][68] aliases A ring (epilogue only)

    const int tid   = threadIdx.x;
    const int lane  = tid & 31;
    const int warp  = tid >> 5;
    const int group = lane >> 2;
    const int tid4  = lane & 3;
    const int wm    = warp >> 1;                 // 0..3 (m)
    const int wn    = warp & 1;                  // 0..1 (n)
    const int ug    = blockIdx.x & 63;           // u-group
    const int m0    = (blockIdx.x >> 6) * 64;    // batch half
    const int u0    = ug * 16;
    const int myflag = ug >> 2;                  // k-chunk this CTA's h-slice feeds

    // Resident Wh slice: smem row j = gate*16 + ul  <->  WhT row n = gate*1024 + u0 + ul
    for (int idx = tid; idx < 64 * 128; idx += 256) {
        int j = idx >> 7, c = idx & 127;
        int n = (j >> 4) * U_ + u0 + (j & 15);
        *(uint4*)&Whs[j * WH_PITCH + c * 8] = *(const uint4*)&g_WhT[(size_t)n * U_ + c * 8];
    }
    __syncthreads();

    const unsigned AAddr = su32(Abuf);
    const unsigned WAddr = su32(Whs);
    const int grpR = lane & 7, sel = lane >> 3;
    const unsigned aoff = ((wm * 16 + grpR + (sel & 1) * 8) * 72 + (sel >> 1) * 8) * 2;
    unsigned boff[2];
#pragma unroll
    for (int p = 0; p < 2; p++)
        boff[p] = ((wn * 32 + p * 16 + grpR + (sel >> 1) * 8) * WH_PITCH + (sel & 1) * 8) * 2;

    // Epilogue ownership: thread t -> u = t&15, rows er+16*i (er = t>>4)
    const int eu = tid & 15;
    const int er = tid >> 4;
    float cst[4] = {0.0f, 0.0f, 0.0f, 0.0f};

    for (int s = 0; s < T_; s++) {
        const __nv_bfloat16* hin  = g_hb[s & 1];
        __nv_bfloat16*       hout = g_hb[(s + 1) & 1];

        // Prefetch this step's xz (bf16, streaming)
        float xzv[4][4];
#pragma unroll
        for (int i = 0; i < 4; i++) {
            size_t base = ((size_t)(m0 + er + 16 * i) * T_ + s) * N4_ + u0 + eu;
#pragma unroll
            for (int g = 0; g < 4; g++)
                xzv[i][g] = ldxz(&g_xz[base + g * U_]);
        }

        float acc[4][4];
#pragma unroll
        for (int j = 0; j < 4; j++)
#pragma unroll
            for (int e = 0; e < 4; e++) acc[j][e] = 0.0f;

        auto issueA = [&](int stage, int buf) {
            unsigned dst = AAddr + buf * RA_STRIDE * 2;
            const __nv_bfloat16* src = hin + m0 * U_ + stage * 64;
#pragma unroll
            for (int i = 0; i < 2; i++) {
                int idx = tid + 256 * i;            // 64 rows x 8 units
                int r = idx >> 3, c = idx & 7;
                cpa16(dst + (r * 72 + c * 8) * 2, src + r * U_ + c * 8);
            }
            cpcommit();
        };

        if (s > 0 && tid == 0) {
            wait_chunk(&g_cflag[s - 1][0]);
            wait_chunk(&g_cflag[s - 1][1]);
        }
        __syncthreads();
        issueA(0, 0);
        issueA(1, 1);

        for (int stg = 0; stg < 16; stg++) {
            if (stg < 15) { CPWAIT(1); } else { CPWAIT(0); }
            if (s > 0 && tid == 0 && stg + 2 < 16)
                wait_chunk(&g_cflag[s - 1][stg + 2]);
            __syncthreads();
            if (stg + 2 < 16) issueA(stg + 2, (stg + 2) % 3);

            unsigned abase = AAddr + (stg % 3) * RA_STRIDE * 2 + aoff;
            unsigned kg = stg * 128;                // 64 bf16 = 128 B
#pragma unroll
            for (int kk4 = 0; kk4 < 4; kk4++) {
                unsigned koff = kk4 * 32;
                unsigned a[4], b0[4], b1[4];
                ldsm4(a,  abase + koff);
                ldsm4(b0, WAddr + boff[0] + kg + koff);
                ldsm4(b1, WAddr + boff[1] + kg + koff);
                mma16816(acc[0], a, b0[0], b0[1]);
                mma16816(acc[1], a, b0[2], b0[3]);
                mma16816(acc[2], a, b1[0], b1[1]);
                mma16816(acc[3], a, b1[2], b1[3]);
            }
        }

        // Write z tiles to smem (aliases A ring; mma + cp.async all done)
        __syncthreads();
#pragma unroll
        for (int nt = 0; nt < 4; nt++) {
            int zr = wm * 16 + group;
            int zc = wn * 32 + nt * 8 + tid4 * 2;
            *(float2*)&zbuf[zr * 68 + zc]       = *(float2*)&acc[nt][0];
            *(float2*)&zbuf[(zr + 8) * 68 + zc] = *(float2*)&acc[nt][2];
        }
        __syncthreads();

        // Gate recombination (cols: gate*16 + u)
#pragma unroll
        for (int i = 0; i < 4; i++) {
            const int r   = er + 16 * i;
            const float zi = zbuf[r * 68 + eu]      + xzv[i][0];
            const float zf = zbuf[r * 68 + 16 + eu] + xzv[i][1];
            const float zg = zbuf[r * 68 + 32 + eu] + xzv[i][2];
            const float zo = zbuf[r * 68 + 48 + eu] + xzv[i][3];
            float c = sigf(zf) * cst[i] + sigf(zi) * tanhf(zg);
            cst[i] = c;
            float h = sigf(zo) * tanhf(c);
            hout[(m0 + r) * U_ + u0 + eu] = __float2bfloat16(h);
            if (s == T_ - 1) g_hfinal[(m0 + r) * U_ + u0 + eu] = h;
        }

        // Publish this CTA's h-slice for step s+1 consumers
        __threadfence();
        __syncthreads();
        if (tid == 0 && s < T_ - 1) atomicAdd(&g_cflag[s][myflag], 1u);
    }
}

// ---------------------------------------------------------------------------
// Head
// ---------------------------------------------------------------------------
__global__ void head_kernel(const float* __restrict__ W1, const float* __restrict__ b1,
                            const float* __restrict__ W2, const float* __restrict__ b2,
                            float* __restrict__ out) {
    const int b = blockIdx.x;
    const int j = threadIdx.x;     // 0..63
    const float* h = &g_hfinal[b * U_];
    float acc = 0.0f;
#pragma unroll 8
    for (int k = 0; k < U_; k++) acc += h[k] * W1[k * 64 + j];
    acc += b1[j];
    float v = acc * W2[j];
#pragma unroll
    for (int off = 16; off; off >>= 1) v += __shfl_xor_sync(0xffffffffu, v, off);
    __shared__ float ws[2];
    if ((j & 31) == 0) ws[j >> 5] = v;
    __syncthreads();
    if (j == 0) {
        float z = ws[0] + ws[1] + b2[0];
        out[b] = 1.0f / (1.0f + __expf(-z));
    }
}

// ---------------------------------------------------------------------------
// Launch (order chosen so gemm_xz is launch index 3 -> gets ncu-captured)
// ---------------------------------------------------------------------------
extern "C" void kernel_launch(void* const* d_in, const int* in_sizes, int n_in,
                              void* d_out, int out_size) {
    const int*   sent32 = (const int*)d_in[0];
    const float* emb = (const float*)d_in[1];
    const float* Wx  = (const float*)d_in[2];
    const float* Wh  = (const float*)d_in[3];
    const float* b   = (const float*)d_in[4];
    const float* W1  = (const float*)d_in[5];
    const float* b1  = (const float*)d_in[6];
    const float* W2  = (const float*)d_in[7];
    const float* b2  = (const float*)d_in[8];
    float* out = (float*)d_out;

    __nv_bfloat16* wxT; cudaGetSymbolAddress((void**)&wxT, g_WxT);
    __nv_bfloat16* whT; cudaGetSymbolAddress((void**)&whT, g_WhT);

    tok_kernel<<<256, 256>>>(sent32);                                   // 0
    prep_emb<<<(V_ * E_ / 4 + 255) / 256, 256>>>(emb);                  // 1
    transpose_bf16<<<dim3(N4_ / 32, E_ / 32), dim3(32, 8)>>>(Wx, wxT, E_, N4_); // 2

    const int smem_g = (3 * GA_STRIDE + 3 * GB_STRIDE) * (int)sizeof(__nv_bfloat16);
    cudaFuncSetAttribute(gemm_xz, cudaFuncAttributeMaxDynamicSharedMemorySize, smem_g);
    dim3 g1(32, 512);
    gemm_xz<<<g1, 256, smem_g>>>(b);                                    // 3 (profiled)

    transpose_bf16<<<dim3(N4_ / 32, U_ / 32), dim3(32, 8)>>>(Wh, whT, U_, N4_); // 4
    init_state<<<256, 256>>>();                                         // 5

    const int smem_r = (64 * WH_PITCH + 3 * RA_STRIDE) * (int)sizeof(__nv_bfloat16);
    cudaFuncSetAttribute(lstm_recurrence, cudaFuncAttributeMaxDynamicSharedMemorySize, smem_r);
    lstm_recurrence<<<NCTA_REC, 256, smem_r>>>();                       // 6

    head_kernel<<<B_, 64>>>(W1, b1, W2, b2, out);                       // 7
}

// round 7
// speedup vs baseline: 1.5613x; 1.5613x over previous
#include <cuda_runtime.h>
#include <cuda_bf16.h>

// Problem constants
#define B_   128
#define T_   512
#define E_   512
#define U_   1024
#define N4_  4096
#define V_   50257
#define NCTA_REC 128

// ---------------------------------------------------------------------------
// Device scratch
// ---------------------------------------------------------------------------
__device__ __nv_bfloat16  g_xz[268435456];          // (B*T, 4U) bf16 = 512 MB
__device__ __nv_bfloat16  g_embB[V_ * E_];          // emb table bf16
__device__ __nv_bfloat16  g_WxT[N4_ * E_];          // Wx^T (n,k) bf16
__device__ __nv_bfloat16  g_WhT[N4_ * U_];          // Wh^T (n,k) bf16
__device__ __nv_bfloat16  g_hb[2][B_ * U_];         // hidden state bf16, dbl-buffered
__device__ float          g_hfinal[B_ * U_];
__device__ int            g_tok[B_ * T_];
__device__ unsigned       g_cnt[T_ + 8];            // per-step arrival counters
__device__ unsigned       g_flag;                   // release flag (monotonic step id)

// ---------------------------------------------------------------------------
// Helpers
// ---------------------------------------------------------------------------
__device__ __forceinline__ float sigf(float x) { return 1.0f / (1.0f + __expf(-x)); }

__device__ __forceinline__ unsigned su32(const void* p) {
    return (unsigned)__cvta_generic_to_shared(p);
}
__device__ __forceinline__ void cpa16(unsigned dst, const void* src) {
    asm volatile("cp.async.cg.shared.global [%0], [%1], 16;\n" :: "r"(dst), "l"(src));
}
__device__ __forceinline__ void cpcommit() { asm volatile("cp.async.commit_group;\n"); }
#define CPWAIT(n) asm volatile("cp.async.wait_group %0;\n" :: "n"(n))

__device__ __forceinline__ void ldsm4(unsigned* r, unsigned addr) {
    asm volatile("ldmatrix.sync.aligned.m8n8.x4.shared.b16 {%0,%1,%2,%3}, [%4];\n"
        : "=r"(r[0]), "=r"(r[1]), "=r"(r[2]), "=r"(r[3]) : "r"(addr));
}
__device__ __forceinline__ void mma16816(float* c, const unsigned* a, unsigned b0, unsigned b1) {
    asm volatile(
        "mma.sync.aligned.m16n8k16.row.col.f32.bf16.bf16.f32 "
        "{%0,%1,%2,%3}, {%4,%5,%6,%7}, {%8,%9}, {%0,%1,%2,%3};\n"
        : "+f"(c[0]), "+f"(c[1]), "+f"(c[2]), "+f"(c[3])
        : "r"(a[0]), "r"(a[1]), "r"(a[2]), "r"(a[3]), "r"(b0), "r"(b1));
}
__device__ __forceinline__ float ldxz(const __nv_bfloat16* p) {
    unsigned short v;
    asm volatile("ld.global.cs.u16 %0, [%1];" : "=h"(v) : "l"(p));
    __nv_bfloat16_raw r; r.x = v;
    return __bfloat162float((__nv_bfloat16)r);
}

// ---------------------------------------------------------------------------
// Fused token detect + decode (int32/int64 robust)
// ---------------------------------------------------------------------------
__global__ void tok_kernel(const int* __restrict__ s32) {
    __shared__ int snz;
    if (threadIdx.x == 0) snz = 0;
    __syncthreads();
    int nz = 0;
    for (int i = threadIdx.x; i < 1024; i += 256) nz |= s32[2 * i + 1];
    if (nz) atomicOr(&snz, 1);
    __syncthreads();
    const int is64 = (snz == 0);
    int i = blockIdx.x * blockDim.x + threadIdx.x;
    if (i < B_ * T_) {
        int t = is64 ? s32[2 * i] : s32[i];
        if (t < 0 || t >= V_) t = 0;
        g_tok[i] = t;
    }
}

// ---------------------------------------------------------------------------
// Prep kernels
// ---------------------------------------------------------------------------
__global__ void prep_emb(const float* __restrict__ emb) {
    int i = blockIdx.x * blockDim.x + threadIdx.x;
    if (i < (V_ * E_) / 4) {
        float4 v = *(const float4*)&emb[(size_t)i * 4];
        __nv_bfloat162 p0, p1;
        p0.x = __float2bfloat16(v.x); p0.y = __float2bfloat16(v.y);
        p1.x = __float2bfloat16(v.z); p1.y = __float2bfloat16(v.w);
        *(__nv_bfloat162*)&g_embB[(size_t)i * 4]     = p0;
        *(__nv_bfloat162*)&g_embB[(size_t)i * 4 + 2] = p1;
    }
}

__global__ void transpose_bf16(const float* __restrict__ src, __nv_bfloat16* __restrict__ dst,
                               int R, int C) {
    __shared__ float tile[32][33];
    int c0 = blockIdx.x * 32, r0 = blockIdx.y * 32;
    int tx = threadIdx.x, ty = threadIdx.y;
#pragma unroll
    for (int i = 0; i < 4; i++)
        tile[ty + 8 * i][tx] = src[(size_t)(r0 + ty + 8 * i) * C + c0 + tx];
    __syncthreads();
#pragma unroll
    for (int i = 0; i < 4; i++)
        dst[(size_t)(c0 + ty + 8 * i) * R + r0 + tx] = __float2bfloat16(tile[tx][ty + 8 * i]);
}

__global__ void init_state() {
    int i = blockIdx.x * blockDim.x + threadIdx.x;
    if (i < (B_ * U_) / 2) ((unsigned*)g_hb[0])[i] = 0u;
    if (i < T_ + 8) g_cnt[i] = 0u;
    if (i == 0) g_flag = 0u;
}

// ---------------------------------------------------------------------------
// GEMM1: xz = embB[tok] @ Wx + b.  M=65536, N=4096, K=512. bf16 output.
// Tile 128x128, BK=64, 256 thr, 3-stage cp.async, ldmatrix + HMMA bf16.
// ---------------------------------------------------------------------------
#define GA_STRIDE (128 * 72)
#define GB_STRIDE (128 * 72)

__global__ void __launch_bounds__(256, 2)
gemm_xz(const float* __restrict__ bias) {
    extern __shared__ __nv_bfloat16 sm[];
    __nv_bfloat16* As = sm;
    __nv_bfloat16* Bs = sm + 3 * GA_STRIDE;
    __shared__ int   tok[128];
    __shared__ float bsm[128];

    const int tid   = threadIdx.x;
    const int lane  = tid & 31;
    const int warp  = tid >> 5;
    const int group = lane >> 2;
    const int tid4  = lane & 3;
    const int wm    = warp >> 1;
    const int wn    = warp & 1;
    const int m0 = blockIdx.y * 128;
    const int n0 = blockIdx.x * 128;

    if (tid < 128) tok[tid] = g_tok[m0 + tid];
    if (tid >= 128) bsm[tid - 128] = bias[n0 + tid - 128];
    __syncthreads();

    const unsigned AsAddr = su32(As);
    const unsigned BsAddr = su32(Bs);
    const int grpR = lane & 7, sel = lane >> 3;
    unsigned aoff[2];
#pragma unroll
    for (int mt = 0; mt < 2; mt++)
        aoff[mt] = ((wm * 32 + mt * 16 + grpR + (sel & 1) * 8) * 72 + (sel >> 1) * 8) * 2;
    unsigned boff[4];
#pragma unroll
    for (int p = 0; p < 4; p++)
        boff[p] = ((wn * 64 + p * 16 + grpR + (sel >> 1) * 8) * 72 + (sel & 1) * 8) * 2;

    auto issue = [&](int stage, int buf) {
        int k0 = stage * 64;
        unsigned adst = AsAddr + buf * GA_STRIDE * 2;
        unsigned bdst = BsAddr + buf * GB_STRIDE * 2;
#pragma unroll
        for (int i = 0; i < 4; i++) {
            int idx = tid + 256 * i;
            int r = idx >> 3, c = idx & 7;
            cpa16(adst + (r * 72 + c * 8) * 2, g_embB + (size_t)tok[r] * E_ + k0 + c * 8);
        }
#pragma unroll
        for (int i = 0; i < 4; i++) {
            int idx = tid + 256 * i;
            int r = idx >> 3, c = idx & 7;
            cpa16(bdst + (r * 72 + c * 8) * 2, g_WxT + (size_t)(n0 + r) * E_ + k0 + c * 8);
        }
        cpcommit();
    };

    float acc[2][8][4];
#pragma unroll
    for (int i = 0; i < 2; i++)
#pragma unroll
        for (int j = 0; j < 8; j++)
#pragma unroll
            for (int e = 0; e < 4; e++) acc[i][j][e] = 0.0f;

    issue(0, 0);
    issue(1, 1);

    for (int stg = 0; stg < 8; stg++) {
        if (stg < 7) { CPWAIT(1); } else { CPWAIT(0); }
        __syncthreads();
        if (stg + 2 < 8) issue(stg + 2, (stg + 2) % 3);

        unsigned abase = AsAddr + (stg % 3) * GA_STRIDE * 2;
        unsigned bbase = BsAddr + (stg % 3) * GB_STRIDE * 2;
#pragma unroll
        for (int kk4 = 0; kk4 < 4; kk4++) {
            unsigned koff = kk4 * 32;
            unsigned a[2][4];
            ldsm4(a[0], abase + aoff[0] + koff);
            ldsm4(a[1], abase + aoff[1] + koff);
#pragma unroll
            for (int p = 0; p < 4; p++) {
                unsigned bb[4];
                ldsm4(bb, bbase + boff[p] + koff);
#pragma unroll
                for (int mt = 0; mt < 2; mt++) {
                    mma16816(acc[mt][2 * p],     a[mt], bb[0], bb[1]);
                    mma16816(acc[mt][2 * p + 1], a[mt], bb[2], bb[3]);
                }
            }
        }
    }

#pragma unroll
    for (int mt = 0; mt < 2; mt++) {
#pragma unroll
        for (int nt = 0; nt < 8; nt++) {
            int gr = m0 + wm * 32 + mt * 16 + group;
            int gc = n0 + wn * 64 + nt * 8 + tid4 * 2;
            float bv0 = bsm[gc - n0], bv1 = bsm[gc - n0 + 1];
            __nv_bfloat162 p0, p1;
            p0.x = __float2bfloat16(acc[mt][nt][0] + bv0);
            p0.y = __float2bfloat16(acc[mt][nt][1] + bv1);
            p1.x = __float2bfloat16(acc[mt][nt][2] + bv0);
            p1.y = __float2bfloat16(acc[mt][nt][3] + bv1);
            *(__nv_bfloat162*)&g_xz[(size_t)gr * N4_ + gc]       = p0;
            *(__nv_bfloat162*)&g_xz[(size_t)(gr + 8) * N4_ + gc] = p1;
        }
    }
}

// ---------------------------------------------------------------------------
// Persistent LSTM recurrence. 128 CTAs = 2 m-halves x 64 u-groups, 256 thr.
// z[64][64] = h[64,1024] @ WhT[64,1024]^T (cols = 4 gates x 16 u).
// Wh slice resident in smem; A ring 4 x [64][72] (CPWAIT(2) depth);
// epilogue z-buffer aliases A ring. Sync: single arrive-counter + release flag.
// ---------------------------------------------------------------------------
#define RA_STRIDE (64 * 72)
#define WH_PITCH  1032

__global__ void __launch_bounds__(256, 1)
lstm_recurrence() {
    extern __shared__ __nv_bfloat16 sm[];
    __nv_bfloat16* Whs  = sm;                    // [64][1032]
    __nv_bfloat16* Abuf = sm + 64 * WH_PITCH;    // 4 x [64][72]
    float* zbuf = (float*)Abuf;                  // [64][68] aliases A ring (epilogue only)

    const int tid   = threadIdx.x;
    const int lane  = tid & 31;
    const int warp  = tid >> 5;
    const int group = lane >> 2;
    const int tid4  = lane & 3;
    const int wm    = warp >> 1;                 // 0..3 (m)
    const int wn    = warp & 1;                  // 0..1 (n)
    const int m0    = (blockIdx.x >> 6) * 64;    // batch half
    const int u0    = (blockIdx.x & 63) * 16;    // u-group

    // Resident Wh slice: smem row j = gate*16 + ul  <->  WhT row n = gate*1024 + u0 + ul
    for (int idx = tid; idx < 64 * 128; idx += 256) {
        int j = idx >> 7, c = idx & 127;
        int n = (j >> 4) * U_ + u0 + (j & 15);
        *(uint4*)&Whs[j * WH_PITCH + c * 8] = *(const uint4*)&g_WhT[(size_t)n * U_ + c * 8];
    }
    __syncthreads();

    const unsigned AAddr = su32(Abuf);
    const unsigned WAddr = su32(Whs);
    const int grpR = lane & 7, sel = lane >> 3;
    const unsigned aoff = ((wm * 16 + grpR + (sel & 1) * 8) * 72 + (sel >> 1) * 8) * 2;
    unsigned boff[2];
#pragma unroll
    for (int p = 0; p < 2; p++)
        boff[p] = ((wn * 32 + p * 16 + grpR + (sel >> 1) * 8) * WH_PITCH + (sel & 1) * 8) * 2;

    // Epilogue ownership: thread t -> u = t&15, rows er+16*i (er = t>>4)
    const int eu = tid & 15;
    const int er = tid >> 4;
    float cst[4] = {0.0f, 0.0f, 0.0f, 0.0f};

    for (int s = 0; s < T_; s++) {
        const __nv_bfloat16* hin  = g_hb[s & 1];
        __nv_bfloat16*       hout = g_hb[(s + 1) & 1];

        // Prefetch this step's xz (bf16, streaming)
        float xzv[4][4];
#pragma unroll
        for (int i = 0; i < 4; i++) {
            size_t base = ((size_t)(m0 + er + 16 * i) * T_ + s) * N4_ + u0 + eu;
#pragma unroll
            for (int g = 0; g < 4; g++)
                xzv[i][g] = ldxz(&g_xz[base + g * U_]);
        }

        float acc[4][4];
#pragma unroll
        for (int j = 0; j < 4; j++)
#pragma unroll
            for (int e = 0; e < 4; e++) acc[j][e] = 0.0f;

        auto issueA = [&](int stage, int buf) {
            unsigned dst = AAddr + buf * RA_STRIDE * 2;
            const __nv_bfloat16* src = hin + m0 * U_ + stage * 64;
#pragma unroll
            for (int i = 0; i < 2; i++) {
                int idx = tid + 256 * i;            // 64 rows x 8 units
                int r = idx >> 3, c = idx & 7;
                cpa16(dst + (r * 72 + c * 8) * 2, src + r * U_ + c * 8);
            }
            cpcommit();
        };

        issueA(0, 0);
        issueA(1, 1);
        issueA(2, 2);

        for (int stg = 0; stg < 16; stg++) {
            if (stg < 14) { CPWAIT(2); } else if (stg == 14) { CPWAIT(1); } else { CPWAIT(0); }
            __syncthreads();
            if (stg + 3 < 16) issueA(stg + 3, (stg + 3) & 3);

            unsigned abase = AAddr + (stg & 3) * RA_STRIDE * 2 + aoff;
            unsigned kg = stg * 128;                // 64 bf16 = 128 B
#pragma unroll
            for (int kk4 = 0; kk4 < 4; kk4++) {
                unsigned koff = kk4 * 32;
                unsigned a[4], b0[4], b1[4];
                ldsm4(a,  abase + koff);
                ldsm4(b0, WAddr + boff[0] + kg + koff);
                ldsm4(b1, WAddr + boff[1] + kg + koff);
                mma16816(acc[0], a, b0[0], b0[1]);
                mma16816(acc[1], a, b0[2], b0[3]);
                mma16816(acc[2], a, b1[0], b1[1]);
                mma16816(acc[3], a, b1[2], b1[3]);
            }
        }

        // Write z tiles to smem (aliases A ring; mma + cp.async all done)
        __syncthreads();
#pragma unroll
        for (int nt = 0; nt < 4; nt++) {
            int zr = wm * 16 + group;
            int zc = wn * 32 + nt * 8 + tid4 * 2;
            *(float2*)&zbuf[zr * 68 + zc]       = *(float2*)&acc[nt][0];
            *(float2*)&zbuf[(zr + 8) * 68 + zc] = *(float2*)&acc[nt][2];
        }
        __syncthreads();

        // Gate recombination (cols: gate*16 + u)
#pragma unroll
        for (int i = 0; i < 4; i++) {
            const int r   = er + 16 * i;
            const float zi = zbuf[r * 68 + eu]      + xzv[i][0];
            const float zf = zbuf[r * 68 + 16 + eu] + xzv[i][1];
            const float zg = zbuf[r * 68 + 32 + eu] + xzv[i][2];
            const float zo = zbuf[r * 68 + 48 + eu] + xzv[i][3];
            float c = sigf(zf) * cst[i] + sigf(zi) * tanhf(zg);
            cst[i] = c;
            float h = sigf(zo) * tanhf(c);
            hout[(m0 + r) * U_ + u0 + eu] = __float2bfloat16(h);
            if (s == T_ - 1) g_hfinal[(m0 + r) * U_ + u0 + eu] = h;
        }

        // Inter-CTA barrier: atomic arrive + acquire-load poll on release flag
        if (s < T_ - 1) {
            __syncthreads();
            if (tid == 0) {
                __threadfence();
                unsigned old = atomicAdd(&g_cnt[s], 1u);
                if (old == NCTA_REC - 1) {
                    asm volatile("st.release.gpu.global.u32 [%0], %1;"
                                 :: "l"(&g_flag), "r"((unsigned)(s + 1)) : "memory");
                } else {
                    unsigned v;
                    do {
                        asm volatile("ld.acquire.gpu.global.u32 %0, [%1];"
                                     : "=r"(v) : "l"(&g_flag) : "memory");
                    } while ((int)v < s + 1);
                }
            }
            __syncthreads();
        }
    }
}

// ---------------------------------------------------------------------------
// Head
// ---------------------------------------------------------------------------
__global__ void head_kernel(const float* __restrict__ W1, const float* __restrict__ b1,
                            const float* __restrict__ W2, const float* __restrict__ b2,
                            float* __restrict__ out) {
    const int b = blockIdx.x;
    const int j = threadIdx.x;     // 0..63
    const float* h = &g_hfinal[b * U_];
    float acc = 0.0f;
#pragma unroll 8
    for (int k = 0; k < U_; k++) acc += h[k] * W1[k * 64 + j];
    acc += b1[j];
    float v = acc * W2[j];
#pragma unroll
    for (int off = 16; off; off >>= 1) v += __shfl_xor_sync(0xffffffffu, v, off);
    __shared__ float ws[2];
    if ((j & 31) == 0) ws[j >> 5] = v;
    __syncthreads();
    if (j == 0) {
        float z = ws[0] + ws[1] + b2[0];
        out[b] = 1.0f / (1.0f + __expf(-z));
    }
}

// ---------------------------------------------------------------------------
// Launch
// ---------------------------------------------------------------------------
extern "C" void kernel_launch(void* const* d_in, const int* in_sizes, int n_in,
                              void* d_out, int out_size) {
    const int*   sent32 = (const int*)d_in[0];
    const float* emb = (const float*)d_in[1];
    const float* Wx  = (const float*)d_in[2];
    const float* Wh  = (const float*)d_in[3];
    const float* b   = (const float*)d_in[4];
    const float* W1  = (const float*)d_in[5];
    const float* b1  = (const float*)d_in[6];
    const float* W2  = (const float*)d_in[7];
    const float* b2  = (const float*)d_in[8];
    float* out = (float*)d_out;

    __nv_bfloat16* wxT; cudaGetSymbolAddress((void**)&wxT, g_WxT);
    __nv_bfloat16* whT; cudaGetSymbolAddress((void**)&whT, g_WhT);

    tok_kernel<<<256, 256>>>(sent32);                                   // 0
    prep_emb<<<(V_ * E_ / 4 + 255) / 256, 256>>>(emb);                  // 1
    transpose_bf16<<<dim3(N4_ / 32, E_ / 32), dim3(32, 8)>>>(Wx, wxT, E_, N4_); // 2

    const int smem_g = (3 * GA_STRIDE + 3 * GB_STRIDE) * (int)sizeof(__nv_bfloat16);
    cudaFuncSetAttribute(gemm_xz, cudaFuncAttributeMaxDynamicSharedMemorySize, smem_g);
    dim3 g1(32, 512);
    gemm_xz<<<g1, 256, smem_g>>>(b);                                    // 3 (profiled)

    transpose_bf16<<<dim3(N4_ / 32, U_ / 32), dim3(32, 8)>>>(Wh, whT, U_, N4_); // 4
    init_state<<<256, 256>>>();                                         // 5

    const int smem_r = (64 * WH_PITCH + 4 * RA_STRIDE) * (int)sizeof(__nv_bfloat16); // 168960
    cudaFuncSetAttribute(lstm_recurrence, cudaFuncAttributeMaxDynamicSharedMemorySize, smem_r);
    lstm_recurrence<<<NCTA_REC, 256, smem_r>>>();                       // 6

    head_kernel<<<B_, 64>>>(W1, b1, W2, b2, out);                       // 7
}